// round 15
// baseline (speedup 1.0000x reference)
#include <cuda_runtime.h>
#include <math.h>

#define N_ATOMS 10000
#define N_PAIRS 100000
#define H 64
#define R 32
#define MAX_Z 100

typedef unsigned long long ull;

// -------- f32x2 packed math helpers (sm_10x) --------
__device__ __forceinline__ ull pk2(float x, float y) {
    ull r; asm("mov.b64 %0,{%1,%2};" : "=l"(r) : "f"(x), "f"(y)); return r;
}
__device__ __forceinline__ float2 up2(ull v) {
    float2 f; asm("mov.b64 {%0,%1},%2;" : "=f"(f.x), "=f"(f.y) : "l"(v)); return f;
}
__device__ __forceinline__ ull dup2(float x) { return pk2(x, x); }
__device__ __forceinline__ ull fma2_(ull a, ull b, ull c) {
    ull d; asm("fma.rn.f32x2 %0,%1,%2,%3;" : "=l"(d) : "l"(a), "l"(b), "l"(c)); return d;
}
__device__ __forceinline__ ull add2_(ull a, ull b) {
    ull d; asm("add.rn.f32x2 %0,%1,%2;" : "=l"(d) : "l"(a), "l"(b)); return d;
}
__device__ __forceinline__ ull mul2_(ull a, ull b) {
    ull d; asm("mul.rn.f32x2 %0,%1,%2;" : "=l"(d) : "l"(a), "l"(b)); return d;
}

// ---------------- scratch ----------------
__device__ __align__(16) float g_U[MAX_Z * H];
__device__ __align__(16) float g_V[MAX_Z * H];
__device__ __align__(16) float g_ltT4[3 * H * H];   // [m][t][g][kk], h=4t+kk
__device__ __align__(16) ull   g_ls1D[64 * 128];    // [k][j], f32x2-duplicated
__device__ __align__(16) float g_ls2T[128 * 192];   // [k][j]
__device__ int   g_counts[N_ATOMS];                 // zero-init; self-cleaned
__device__ int   g_offsets[N_ATOMS + 1];
__device__ int   g_cursor[N_ATOMS];
__device__ unsigned int g_ticket;                   // zero-init; self-cleaned
__device__ __align__(16) float4 g_geoA[N_PAIRS];    // ux,uy,uz,rc (slot-ordered)
__device__ __align__(16) float4 g_geoB[N_PAIRS];    // txx,tyy,tzz,-
__device__ __align__(16) float4 g_geoC[N_PAIRS];    // txy,txz,tyz,-
__device__ __align__(16) ull g_f1[N_PAIRS * 32];    // f1 per (pair, h-pair)
__device__ __align__(16) ull g_f2[N_PAIRS * 32];
__device__ __align__(16) ull g_f3[N_PAIRS * 32];
__device__ __align__(16) float g_comp[10][N_ATOMS * H];
__device__ __align__(16) float g_tnorm[N_ATOMS * H];

#define RBF_START 0.60653065971263342f
#define RBF_ALPHA 10.0f

#define HIST_BLOCKS 391
#define UV_BLOCKS   25
#define LTT_BLOCKS  48
#define L1T_BLOCKS  32
#define L2T_BLOCKS  96
#define PRE_BLOCKS  (HIST_BLOCKS + UV_BLOCKS + LTT_BLOCKS + L1T_BLOCKS + L2T_BLOCKS)

// ---------------- K_pre: hist + UV + transposes, then LAST BLOCK runs the scan --
__global__ void __launch_bounds__(256) k_pre(
    const int* __restrict__ src,
    const float* __restrict__ emb, const float* __restrict__ w2,
    const float* __restrict__ b2,
    const float* __restrict__ lt0, const float* __restrict__ lt1,
    const float* __restrict__ lt2,
    const float* __restrict__ ls1w, const float* __restrict__ ls2w) {
    int b = blockIdx.x;
    int tid = threadIdx.x;
    if (b < HIST_BLOCKS) {
        int i = b * 256 + tid;
        if (i < N_PAIRS) atomicAdd(&g_counts[src[i]], 1);
    } else if (b < HIST_BLOCKS + UV_BLOCKS) {
        __shared__ float se[4][H];
        int ty = tid >> 6;
        int h  = tid & 63;
        int t  = (b - HIST_BLOCKS) * 4 + ty;
        se[ty][h] = emb[t * H + h];
        __syncthreads();
        float u = b2[h];
        float v = 0.0f;
        const float* wr = w2 + h * 2 * H;
#pragma unroll
        for (int k = 0; k < H; k++) {
            u += se[ty][k] * wr[k];
            v += se[ty][k] * wr[H + k];
        }
        g_U[t * H + h] = u;
        g_V[t * H + h] = v;
    } else if (b < HIST_BLOCKS + UV_BLOCKS + LTT_BLOCKS) {
        int idx = (b - HIST_BLOCKS - UV_BLOCKS) * 256 + tid;   // < 12288
        int m = idx >> 12;
        int rem = idx & 4095;
        int t = rem >> 8, g = (rem >> 2) & 63, kk = rem & 3;
        int h = 4 * t + kk;
        const float* s = (m == 0) ? lt0 : (m == 1) ? lt1 : lt2;
        g_ltT4[idx] = s[g * 64 + h];
    } else if (b < HIST_BLOCKS + UV_BLOCKS + LTT_BLOCKS + L1T_BLOCKS) {
        int idx = (b - HIST_BLOCKS - UV_BLOCKS - LTT_BLOCKS) * 256 + tid;  // < 8192
        int k = idx >> 7, j = idx & 127;
        g_ls1D[idx] = dup2(ls1w[j * 64 + k]);
    } else {
        int idx = (b - HIST_BLOCKS - UV_BLOCKS - LTT_BLOCKS - L1T_BLOCKS) * 256 + tid;
        int k = idx / 192, j = idx - k * 192;   // idx < 24576
        g_ls2T[idx] = ls2w[j * 128 + k];
    }

    // ---- last-block ticket: the final block to finish runs the scan ----
    __shared__ int s_last;
    __syncthreads();
    if (tid == 0) {
        __threadfence();
        unsigned int t = atomicAdd(&g_ticket, 1u);
        s_last = (t == (unsigned)(PRE_BLOCKS - 1)) ? 1 : 0;
    }
    __syncthreads();
    if (!s_last) return;
    __threadfence();   // acquire all producers' writes

    // scan of g_counts[0..9999] with 256 threads, 40 elems/thread (guarded)
    __shared__ int wsum[8];
    {
        int lane = tid & 31, wid = tid >> 5;
        int base = tid * 40;
        int loc[40];
        int s = 0;
#pragma unroll
        for (int i = 0; i < 40; i++) {
            int idx = base + i;
            int c = (idx < N_ATOMS) ? g_counts[idx] : 0;
            loc[i] = s;
            s += c;
        }
        int v = s;
#pragma unroll
        for (int o = 1; o < 32; o <<= 1) {
            int u = __shfl_up_sync(0xffffffffu, v, o);
            if (lane >= o) v += u;
        }
        if (lane == 31) wsum[wid] = v;
        __syncthreads();
        if (wid == 0 && lane < 8) {
            int x = wsum[lane];
#pragma unroll
            for (int o = 1; o < 8; o <<= 1) {
                int u = __shfl_up_sync(0xffu, x, o);
                if (lane >= o) x += u;
            }
            wsum[lane] = x;
        }
        __syncthreads();
        int wbase = (wid > 0) ? wsum[wid - 1] : 0;
        int excl = wbase + v - s;
#pragma unroll
        for (int i = 0; i < 40; i++) {
            int idx = base + i;
            if (idx < N_ATOMS) {
                int o = excl + loc[i];
                g_offsets[idx] = o;
                g_cursor[idx]  = o;
                g_counts[idx]  = 0;   // restore invariant for next replay
            }
        }
        if (tid == 255) {
            g_offsets[N_ATOMS] = wbase + v;
            g_ticket = 0;             // restore invariant for next replay
        }
    }
}

// ---------------- K_prep: scatter + geometry + rbf + f1/f2/f3 GEMM ----------
#define PREP_SMEM (16384 + 8192 + 32768)
__global__ void __launch_bounds__(256) k_prep(
    const int* __restrict__ src, const int* __restrict__ pdst,
    const int* __restrict__ anum,
    const float* __restrict__ dij, const float* __restrict__ rij,
    const float* __restrict__ dp1w, const float* __restrict__ dp2w,
    const float* __restrict__ dp3w,
    const float* __restrict__ dp1b, const float* __restrict__ dp2b,
    const float* __restrict__ dp3b) {
    extern __shared__ char smraw[];
    ulonglong2* sh_dp12 = reinterpret_cast<ulonglong2*>(smraw);          // [r*32+lane]
    ull*        sh_dp3  = reinterpret_cast<ull*>(smraw + 16384);
    float*      s_rbf   = reinterpret_cast<float*>(smraw + 24576);      // [w][p][r]

    int tid = threadIdx.x;
    for (int e = tid; e < R * 32; e += 256) {
        int r = e >> 5, l = e & 31;
        int h0 = 2 * l, h1 = h0 + 1;
        sh_dp12[e] = make_ulonglong2(pk2(dp1w[h0 * R + r], dp1w[h1 * R + r]),
                                     pk2(dp2w[h0 * R + r], dp2w[h1 * R + r]));
        sh_dp3[e]  = pk2(dp3w[h0 * R + r], dp3w[h1 * R + r]);
    }
    __syncthreads();

    int w = tid >> 5, lane = tid & 31;
    int i = blockIdx.x * 256 + tid;
    if ((i & ~31) >= N_PAIRS) return;     // whole warps only (N_PAIRS % 32 == 0)

    // stage 1: geometry + scatter
    float d = dij[i];
    float rc = (d < 0.5f) ? 0.5f * (__cosf(6.2831853071795865f * d) + 1.0f) : 0.0f;
    int za = anum[src[i]];
    int zd = anum[pdst[i]];
    float rx = rij[3 * i], ry = rij[3 * i + 1], rz = rij[3 * i + 2];
    float inv = 1.0f / d;
    float ux = rx * inv, uy = ry * inv, uz = rz * inv;
    float tr3 = (ux * ux + uy * uy + uz * uz) * (1.0f / 3.0f);
    float ee = __expf(-RBF_ALPHA * d);
    int pos = atomicAdd(&g_cursor[src[i]], 1);
    g_geoA[pos] = make_float4(ux, uy, uz, rc);
    g_geoB[pos] = make_float4(ux * ux - tr3, uy * uy - tr3, uz * uz - tr3, 0.0f);
    g_geoC[pos] = make_float4(ux * uy, ux * uz, uy * uz, 0.0f);

    // stage 2: warp-cooperative rbf -> smem [p][r]
    const float rbf_step = (1.0f - RBF_START) * (1.0f / 31.0f);
    float tb = (1.0f - RBF_START) * (2.0f / 32.0f);
    const float beta = 1.0f / (tb * tb);
    const float mlane = RBF_START + rbf_step * (float)lane;
    float* myrbf = s_rbf + w * 1024;
#pragma unroll 4
    for (int j = 0; j < 32; j++) {
        float ee_b = __shfl_sync(0xffffffffu, ee, j);
        float rc_b = __shfl_sync(0xffffffffu, rc, j);
        float dfm = ee_b - mlane;
        myrbf[j * 32 + lane] = __expf(-beta * dfm * dfm) * rc_b;
    }
    __syncwarp();

    float2 b1v = reinterpret_cast<const float2*>(dp1b)[lane];
    float2 b2v = reinterpret_cast<const float2*>(dp2b)[lane];
    float2 b3v = reinterpret_cast<const float2*>(dp3b)[lane];
    ull b1p = pk2(b1v.x, b1v.y);
    ull b2p = pk2(b2v.x, b2v.y);
    ull b3p = pk2(b3v.x, b3v.y);
    const ull tenp = dup2(10.0f);
    const ull hunp = dup2(100.0f);
    const float2* U2 = reinterpret_cast<const float2*>(g_U);
    const float2* V2 = reinterpret_cast<const float2*>(g_V);

    // stage 3: rbf @ W, fold C, write f1/f2/f3
#pragma unroll 1
    for (int grp = 0; grp < 4; grp++) {
        ull g1[8] = {0,0,0,0,0,0,0,0};
        ull g2[8] = {0,0,0,0,0,0,0,0};
        ull g3[8] = {0,0,0,0,0,0,0,0};
        const float* rb = myrbf + grp * 8 * 32;
#pragma unroll
        for (int r = 0; r < R; r++) {
            ulonglong2 w12 = sh_dp12[r * 32 + lane];
            ull w3 = sh_dp3[r * 32 + lane];
#pragma unroll
            for (int pi = 0; pi < 8; pi++) {
                ull rv = dup2(rb[pi * 32 + r]);
                g1[pi] = fma2_(rv, w12.x, g1[pi]);
                g2[pi] = fma2_(rv, w12.y, g2[pi]);
                g3[pi] = fma2_(rv, w3,    g3[pi]);
            }
        }
#pragma unroll
        for (int pi = 0; pi < 8; pi++) {
            int p = grp * 8 + pi;
            int   pos_b = __shfl_sync(0xffffffffu, pos, p);
            int   za_b  = __shfl_sync(0xffffffffu, za,  p);
            int   zd_b  = __shfl_sync(0xffffffffu, zd,  p);
            float rc_b  = __shfl_sync(0xffffffffu, rc,  p);
            float2 ubv = U2[za_b * 32 + lane];
            float2 vbv = V2[zd_b * 32 + lane];
            ull Cp = pk2(rc_b * (ubv.x + vbv.x), rc_b * (ubv.y + vbv.y));
            g_f1[pos_b * 32 + lane] = mul2_(add2_(g1[pi], b1p), Cp);
            g_f2[pos_b * 32 + lane] = mul2_(mul2_(add2_(g2[pi], b2p), Cp), tenp);
            g_f3[pos_b * 32 + lane] = mul2_(mul2_(add2_(g3[pi], b3p), Cp), hunp);
        }
    }
}

// ---------------- K_pairs: pure streaming accumulate + layernorm ----------------
__global__ void __launch_bounds__(256) k_pairs(
    const float* __restrict__ lng, const float* __restrict__ lnb) {
    int w    = threadIdx.x >> 5;
    int lane = threadIdx.x & 31;
    int a    = blockIdx.x * 8 + w;

    int start = g_offsets[a];
    int end   = g_offsets[a + 1];

    ull cI = 0, wx = 0, wy = 0, wz = 0;
    ull sxx = 0, syy = 0, szz = 0, sxy = 0, sxz = 0, syz = 0;

#pragma unroll 2
    for (int idx = start; idx < end; idx++) {
        ull f1 = g_f1[idx * 32 + lane];
        ull f2 = g_f2[idx * 32 + lane];
        ull f3 = g_f3[idx * 32 + lane];
        float4 gA = g_geoA[idx];
        float4 gB = g_geoB[idx];
        float4 gC = g_geoC[idx];
        cI  = add2_(cI, f1);
        wx  = fma2_(f2, dup2(gA.x), wx);
        wy  = fma2_(f2, dup2(gA.y), wy);
        wz  = fma2_(f2, dup2(gA.z), wz);
        sxx = fma2_(f3, dup2(gB.x), sxx);
        syy = fma2_(f3, dup2(gB.y), syy);
        szz = fma2_(f3, dup2(gB.z), szz);
        sxy = fma2_(f3, dup2(gC.x), sxy);
        sxz = fma2_(f3, dup2(gC.y), sxz);
        syz = fma2_(f3, dup2(gC.z), syz);
    }

    float2 cIf = up2(cI),  wxf = up2(wx),  wyf = up2(wy),  wzf = up2(wz);
    float2 sxxf = up2(sxx), syyf = up2(syy), szzf = up2(szz);
    float2 sxyf = up2(sxy), sxzf = up2(sxz), syzf = up2(syz);

    float tA0 = cIf.x + sxxf.x, tB0 = cIf.x + syyf.x, tC0 = cIf.x + szzf.x;
    float tn0 = tA0*tA0 + tB0*tB0 + tC0*tC0
              + 2.0f * (sxyf.x*sxyf.x + wzf.x*wzf.x + sxzf.x*sxzf.x
                      + wyf.x*wyf.x + syzf.x*syzf.x + wxf.x*wxf.x);
    float tA1 = cIf.y + sxxf.y, tB1 = cIf.y + syyf.y, tC1 = cIf.y + szzf.y;
    float tn1 = tA1*tA1 + tB1*tB1 + tC1*tC1
              + 2.0f * (sxyf.y*sxyf.y + wzf.y*wzf.y + sxzf.y*sxzf.y
                      + wyf.y*wyf.y + syzf.y*syzf.y + wxf.y*wxf.y);

    float ssum = tn0 + tn1;
#pragma unroll
    for (int o = 16; o; o >>= 1) ssum += __shfl_xor_sync(0xffffffffu, ssum, o);
    float mu = ssum * (1.0f / 64.0f);
    float e0 = tn0 - mu, e1 = tn1 - mu;
    float vsum = e0 * e0 + e1 * e1;
#pragma unroll
    for (int o = 16; o; o >>= 1) vsum += __shfl_xor_sync(0xffffffffu, vsum, o);
    float rstd = rsqrtf(vsum * (1.0f / 64.0f) + 1e-5f);

    float2 lg = reinterpret_cast<const float2*>(lng)[lane];
    float2 lb = reinterpret_cast<const float2*>(lnb)[lane];
    float2 nrm;
    nrm.x = e0 * rstd * lg.x + lb.x;
    nrm.y = e1 * rstd * lg.y + lb.y;
    reinterpret_cast<float2*>(g_tnorm)[a * 32 + lane] = nrm;

    int oidx = a * 32 + lane;
    reinterpret_cast<float2*>(g_comp[0])[oidx] = cIf;
    reinterpret_cast<float2*>(g_comp[1])[oidx] = wxf;
    reinterpret_cast<float2*>(g_comp[2])[oidx] = wyf;
    reinterpret_cast<float2*>(g_comp[3])[oidx] = wzf;
    reinterpret_cast<float2*>(g_comp[4])[oidx] = sxxf;
    reinterpret_cast<float2*>(g_comp[5])[oidx] = syyf;
    reinterpret_cast<float2*>(g_comp[6])[oidx] = szzf;
    reinterpret_cast<float2*>(g_comp[7])[oidx] = sxyf;
    reinterpret_cast<float2*>(g_comp[8])[oidx] = sxzf;
    reinterpret_cast<float2*>(g_comp[9])[oidx] = syzf;
}

// ---------------- K_mlpfinal: 16 atoms/block; pinned 2 blocks/SM ----------
// smem (ull): region[5760] (csh [c][h][q]=c*512+h*8+q then res [c][g][q9]=c*576+g*9+q)
//             nshT[512] ([k][q]=k*8+q), h1T[1024] ([aq][j][i]=aq*256+j*2+i),
//             nm float[3072] = 1536 ull ([atom][j2])
#define MLPF_ULL (5760 + 512 + 1024 + 1536)
#define MLPF_SMEM (MLPF_ULL * 8)
__global__ void __launch_bounds__(640, 2) k_mlpfinal(
    const float* __restrict__ ls1b, const float* __restrict__ ls2b,
    float* __restrict__ out) {
    extern __shared__ __align__(16) ull smu[];
    ull*   region = smu;
    ull*   nshT   = smu + 5760;
    ull*   h1T    = smu + 6272;
    float* nm     = reinterpret_cast<float*>(smu + 7296);   // 3072 floats
    float* resf   = reinterpret_cast<float*>(region);

    int tid = threadIdx.x;
    int ab  = blockIdx.x * 16;

    // ---- stage csh [c][h][q]
#pragma unroll
    for (int it = 0; it < 4; it++) {
        int u = it * 640 + tid;          // < 2560
        int q4 = u & 3;
        int h  = (u >> 2) & 63;
        int c  = u >> 8;                 // 0..9
        const float* cp = g_comp[c] + (ab + 4 * q4) * 64 + h;
        float v0 = cp[0], v1 = cp[64], v2 = cp[128], v3 = cp[192];
        *reinterpret_cast<ulonglong2*>(region + c * 512 + h * 8 + 2 * q4) =
            make_ulonglong2(pk2(v0, v1), pk2(v2, v3));
    }
    // ---- stage nshT [k][q]
    if (tid < 256) {
        int q4 = tid & 3;
        int k  = tid >> 2;
        const float* tp = g_tnorm + (ab + 4 * q4) * 64 + k;
        float v0 = tp[0], v1 = tp[64], v2 = tp[128], v3 = tp[192];
        *reinterpret_cast<ulonglong2*>(nshT + k * 8 + 2 * q4) =
            make_ulonglong2(pk2(v0, v1), pk2(v2, v3));
    }
    __syncthreads();

    // ---- channel-mix GEMM: thread=(c,g); weights from packed ltT4 (coalesced LDG.128)
    ull acc[8];
    int c = tid >> 6, g = tid & 63;
    {
        int m = (c == 0) ? 0 : (c < 4) ? 1 : 2;
        const float4* wq = reinterpret_cast<const float4*>(g_ltT4 + m * 4096);
        const ull* csrc = region + c * 512;
#pragma unroll
        for (int i = 0; i < 8; i++) acc[i] = 0ull;
#pragma unroll 4
        for (int t = 0; t < 16; t++) {
            float4 wv = wq[t * 64 + g];
#pragma unroll
            for (int kk = 0; kk < 4; kk++) {
                float ws = (kk == 0) ? wv.x : (kk == 1) ? wv.y : (kk == 2) ? wv.z : wv.w;
                ull wd = dup2(ws);
                const ulonglong2* q =
                    reinterpret_cast<const ulonglong2*>(csrc + (4 * t + kk) * 8);
                ulonglong2 q0 = q[0], q1 = q[1], q2 = q[2], q3 = q[3];
                acc[0] = fma2_(wd, q0.x, acc[0]);
                acc[1] = fma2_(wd, q0.y, acc[1]);
                acc[2] = fma2_(wd, q1.x, acc[2]);
                acc[3] = fma2_(wd, q1.y, acc[3]);
                acc[4] = fma2_(wd, q2.x, acc[4]);
                acc[5] = fma2_(wd, q2.y, acc[5]);
                acc[6] = fma2_(wd, q3.x, acc[6]);
                acc[7] = fma2_(wd, q3.y, acc[7]);
            }
        }
    }
    __syncthreads();   // all csh reads done; region reusable

    // ---- write res [c][g][q-pad9] + MLP layer 1 (pre-duplicated ls1D LDG.64)
    {
        ull* rp = region + c * 576 + g * 9;
#pragma unroll
        for (int i = 0; i < 8; i++) rp[i] = acc[i];
    }
    if (tid < 512) {
        int j = tid & 127, hq = tid >> 7;       // hq 0..3 -> atoms 4hq..4hq+3
        ull bp = dup2(ls1b[j]);
        ull a0 = bp, a1 = bp;
        const ull* wcol = g_ls1D + j;
#pragma unroll 8
        for (int k = 0; k < 64; k++) {
            ull wd = wcol[k * 128];
            ulonglong2 hv = *reinterpret_cast<const ulonglong2*>(nshT + k * 8 + 2 * hq);
            a0 = fma2_(wd, hv.x, a0);
            a1 = fma2_(wd, hv.y, a1);
        }
        float2 f0 = up2(a0), f1v = up2(a1);
        float r0 = f0.x  / (1.0f + __expf(-f0.x));
        float r1 = f0.y  / (1.0f + __expf(-f0.y));
        float r2 = f1v.x / (1.0f + __expf(-f1v.x));
        float r3 = f1v.y / (1.0f + __expf(-f1v.y));
        *reinterpret_cast<ulonglong2*>(h1T + hq * 256 + j * 2) =
            make_ulonglong2(pk2(r0, r1), pk2(r2, r3));
    }
    __syncthreads();

    // ---- MLP layer 2: 384 threads = (jp 0..95, atom-quad aq 0..3); 4 accs each
    if (tid < 384) {
        int jp = tid % 96, aq = tid / 96;
        int j2a = 2 * jp, j2b = j2a + 1;
        ull acc2[4];
        {
            ull bpa = dup2(ls2b[j2a]);
            ull bpb = dup2(ls2b[j2b]);
            acc2[0] = bpa; acc2[1] = bpa;
            acc2[2] = bpb; acc2[3] = bpb;
        }
        const ull* hq = h1T + aq * 256;   // atoms 4aq..4aq+3
#pragma unroll 4
        for (int k = 0; k < 128; k++) {
            float2 wp = reinterpret_cast<const float2*>(g_ls2T + k * 192)[jp];
            ull wda = dup2(wp.x), wdb = dup2(wp.y);
            ulonglong2 hv = *reinterpret_cast<const ulonglong2*>(hq + k * 2);
            acc2[0] = fma2_(wda, hv.x, acc2[0]);
            acc2[1] = fma2_(wda, hv.y, acc2[1]);
            acc2[2] = fma2_(wdb, hv.x, acc2[2]);
            acc2[3] = fma2_(wdb, hv.y, acc2[3]);
        }
#pragma unroll
        for (int i = 0; i < 2; i++) {
            int a0i = 4 * aq + 2 * i;
            float2 fa = up2(acc2[i]);
            nm[a0i * 192 + j2a]       = fa.x / (1.0f + __expf(-fa.x));
            nm[(a0i + 1) * 192 + j2a] = fa.y / (1.0f + __expf(-fa.y));
            float2 fb = up2(acc2[2 + i]);
            nm[a0i * 192 + j2b]       = fb.x / (1.0f + __expf(-fb.x));
            nm[(a0i + 1) * 192 + j2b] = fb.y / (1.0f + __expf(-fb.y));
        }
    }
    __syncthreads();

    // ---- assemble 3x3 outputs: thread = (aa = tid/40, w0 = tid%40), stride 40
    {
        int aa = tid / 40;            // 0..15 (640 = 16*40)
        int w0 = tid - aa * 40;       // 0..39
        int g2 = w0 / 9;
        int ij = w0 - g2 * 9;
        float* ob = out + (ab + aa) * 576;
        const float* nmb = nm + aa * 192;
        const float* rb = resf + aa;
        for (int idx = w0; idx < 576; idx += 40) {
            int i3 = (ij * 11) >> 5;
            int jc = ij - i3 * 3;
            bool dg = (i3 == jc);
            int sidx = dg ? (4 + i3) : (6 + i3 + jc);
            int aidx = dg ? 1 : (4 - (i3 + jc));
            float sgn = dg ? 0.0f : ((((i3 - jc) + 3) % 3 == 1) ? 1.0f : -1.0f);
            float n0 = nmb[g2 * 3 + 0];
            float n1 = nmb[g2 * 3 + 1];
            float n2 = nmb[g2 * 3 + 2];
            float cIv = rb[g2 * 18];
            float av  = rb[aidx * 1152 + g2 * 18];
            float sv  = rb[sidx * 1152 + g2 * 18];
            float iv = dg ? cIv : 0.0f;
            ob[idx] = iv * n0 + sgn * av * n1 + sv * n2;
            ij += 4; g2 += 4;
            if (ij >= 9) { ij -= 9; g2 += 1; }
        }
    }
}

// ---------------- launch ----------------
extern "C" void kernel_launch(void* const* d_in, const int* in_sizes, int n_in,
                              void* d_out, int out_size) {
    const int*   anum  = (const int*)d_in[0];
    const int*   psrc  = (const int*)d_in[1];
    const int*   pdst  = psrc + N_PAIRS;
    const float* dij   = (const float*)d_in[2];
    const float* rij   = (const float*)d_in[3];
    const float* emb   = (const float*)d_in[4];
    const float* e2w   = (const float*)d_in[5];
    const float* e2b   = (const float*)d_in[6];
    const float* dp1w  = (const float*)d_in[7];
    const float* dp1b  = (const float*)d_in[8];
    const float* dp2w  = (const float*)d_in[9];
    const float* dp2b  = (const float*)d_in[10];
    const float* dp3w  = (const float*)d_in[11];
    const float* dp3b  = (const float*)d_in[12];
    const float* lt0   = (const float*)d_in[13];
    const float* lt1   = (const float*)d_in[14];
    const float* lt2   = (const float*)d_in[15];
    const float* ls1w  = (const float*)d_in[16];
    const float* ls1b  = (const float*)d_in[17];
    const float* ls2w  = (const float*)d_in[18];
    const float* ls2b  = (const float*)d_in[19];
    const float* lng   = (const float*)d_in[20];
    const float* lnb   = (const float*)d_in[21];
    float* out = (float*)d_out;

    cudaFuncSetAttribute(k_prep, cudaFuncAttributeMaxDynamicSharedMemorySize, PREP_SMEM);
    cudaFuncSetAttribute(k_mlpfinal, cudaFuncAttributeMaxDynamicSharedMemorySize, MLPF_SMEM);

    k_pre<<<PRE_BLOCKS, 256>>>(psrc, emb, e2w, e2b, lt0, lt1, lt2, ls1w, ls2w);
    k_prep<<<(N_PAIRS + 255) / 256, 256, PREP_SMEM>>>(psrc, pdst, anum, dij, rij,
                                                      dp1w, dp2w, dp3w,
                                                      dp1b, dp2b, dp3b);
    k_pairs<<<N_ATOMS / 8, 256>>>(lng, lnb);
    k_mlpfinal<<<N_ATOMS / 16, 640, MLPF_SMEM>>>(ls1b, ls2b, out);
}

// round 17
// speedup vs baseline: 1.0592x; 1.0592x over previous
#include <cuda_runtime.h>
#include <math.h>

#define N_ATOMS 10000
#define N_PAIRS 100000
#define H 64
#define R 32
#define MAX_Z 100

typedef unsigned long long ull;

// -------- f32x2 packed math helpers (sm_10x) --------
__device__ __forceinline__ ull pk2(float x, float y) {
    ull r; asm("mov.b64 %0,{%1,%2};" : "=l"(r) : "f"(x), "f"(y)); return r;
}
__device__ __forceinline__ float2 up2(ull v) {
    float2 f; asm("mov.b64 {%0,%1},%2;" : "=f"(f.x), "=f"(f.y) : "l"(v)); return f;
}
__device__ __forceinline__ ull dup2(float x) { return pk2(x, x); }
__device__ __forceinline__ ull fma2_(ull a, ull b, ull c) {
    ull d; asm("fma.rn.f32x2 %0,%1,%2,%3;" : "=l"(d) : "l"(a), "l"(b), "l"(c)); return d;
}
__device__ __forceinline__ ull add2_(ull a, ull b) {
    ull d; asm("add.rn.f32x2 %0,%1,%2;" : "=l"(d) : "l"(a), "l"(b)); return d;
}
__device__ __forceinline__ ull mul2_(ull a, ull b) {
    ull d; asm("mul.rn.f32x2 %0,%1,%2;" : "=l"(d) : "l"(a), "l"(b)); return d;
}

// ---------------- scratch ----------------
__device__ __align__(16) float g_U[MAX_Z * H];
__device__ __align__(16) float g_V[MAX_Z * H];
__device__ __align__(16) float g_ltT4[3 * H * H];   // [m][t][g][kk], h=4t+kk
__device__ __align__(16) ull   g_ls1D[64 * 128];    // [k][j], f32x2-duplicated
__device__ __align__(16) float g_ls2T[128 * 192];   // [k][j]
__device__ int   g_counts[N_ATOMS];                 // zero-init; self-cleaned
__device__ int   g_offsets[N_ATOMS + 1];
__device__ int   g_cursor[N_ATOMS];
__device__ unsigned int g_ticket;                   // zero-init; self-cleaned
__device__ __align__(16) float4 g_geoA[N_PAIRS];    // ux,uy,uz,rc (slot-ordered)
__device__ __align__(16) float4 g_geoB[N_PAIRS];    // txx,tyy,tzz,-
__device__ __align__(16) float4 g_geoC[N_PAIRS];    // txy,txz,tyz,-
__device__ __align__(16) ull g_f1[N_PAIRS * 32];    // f1 per (pair, h-pair)
__device__ __align__(16) ull g_f2[N_PAIRS * 32];
__device__ __align__(16) ull g_f3[N_PAIRS * 32];
__device__ __align__(16) float g_comp[10][N_ATOMS * H];
__device__ __align__(16) float g_tnorm[N_ATOMS * H];

#define RBF_START 0.60653065971263342f
#define RBF_ALPHA 10.0f

#define HIST_BLOCKS 391
#define UV_BLOCKS   25
#define LTT_BLOCKS  48
#define L1T_BLOCKS  32
#define L2T_BLOCKS  96
#define PRE_BLOCKS  (HIST_BLOCKS + UV_BLOCKS + LTT_BLOCKS + L1T_BLOCKS + L2T_BLOCKS)

// ---------------- K_pre: hist + UV + transposes, then LAST BLOCK runs the scan --
__global__ void __launch_bounds__(256) k_pre(
    const int* __restrict__ src,
    const float* __restrict__ emb, const float* __restrict__ w2,
    const float* __restrict__ b2,
    const float* __restrict__ lt0, const float* __restrict__ lt1,
    const float* __restrict__ lt2,
    const float* __restrict__ ls1w, const float* __restrict__ ls2w) {
    int b = blockIdx.x;
    int tid = threadIdx.x;
    if (b < HIST_BLOCKS) {
        int i = b * 256 + tid;
        if (i < N_PAIRS) atomicAdd(&g_counts[src[i]], 1);
    } else if (b < HIST_BLOCKS + UV_BLOCKS) {
        __shared__ float se[4][H];
        int ty = tid >> 6;
        int h  = tid & 63;
        int t  = (b - HIST_BLOCKS) * 4 + ty;
        se[ty][h] = emb[t * H + h];
        __syncthreads();
        float u = b2[h];
        float v = 0.0f;
        const float* wr = w2 + h * 2 * H;
#pragma unroll
        for (int k = 0; k < H; k++) {
            u += se[ty][k] * wr[k];
            v += se[ty][k] * wr[H + k];
        }
        g_U[t * H + h] = u;
        g_V[t * H + h] = v;
    } else if (b < HIST_BLOCKS + UV_BLOCKS + LTT_BLOCKS) {
        int idx = (b - HIST_BLOCKS - UV_BLOCKS) * 256 + tid;   // < 12288
        int m = idx >> 12;
        int rem = idx & 4095;
        int t = rem >> 8, g = (rem >> 2) & 63, kk = rem & 3;
        int h = 4 * t + kk;
        const float* s = (m == 0) ? lt0 : (m == 1) ? lt1 : lt2;
        g_ltT4[idx] = s[g * 64 + h];
    } else if (b < HIST_BLOCKS + UV_BLOCKS + LTT_BLOCKS + L1T_BLOCKS) {
        int idx = (b - HIST_BLOCKS - UV_BLOCKS - LTT_BLOCKS) * 256 + tid;  // < 8192
        int k = idx >> 7, j = idx & 127;
        g_ls1D[idx] = dup2(ls1w[j * 64 + k]);
    } else {
        int idx = (b - HIST_BLOCKS - UV_BLOCKS - LTT_BLOCKS - L1T_BLOCKS) * 256 + tid;
        int k = idx / 192, j = idx - k * 192;   // idx < 24576
        g_ls2T[idx] = ls2w[j * 128 + k];
    }

    // ---- last-block ticket: the final block to finish runs the scan ----
    __shared__ int s_last;
    __syncthreads();
    if (tid == 0) {
        __threadfence();
        unsigned int t = atomicAdd(&g_ticket, 1u);
        s_last = (t == (unsigned)(PRE_BLOCKS - 1)) ? 1 : 0;
    }
    __syncthreads();
    if (!s_last) return;
    __threadfence();   // acquire all producers' writes

    // scan of g_counts[0..9999] with 256 threads, 40 elems/thread (guarded)
    __shared__ int wsum[8];
    {
        int lane = tid & 31, wid = tid >> 5;
        int base = tid * 40;
        int loc[40];
        int s = 0;
#pragma unroll
        for (int i = 0; i < 40; i++) {
            int idx = base + i;
            int c = (idx < N_ATOMS) ? g_counts[idx] : 0;
            loc[i] = s;
            s += c;
        }
        int v = s;
#pragma unroll
        for (int o = 1; o < 32; o <<= 1) {
            int u = __shfl_up_sync(0xffffffffu, v, o);
            if (lane >= o) v += u;
        }
        if (lane == 31) wsum[wid] = v;
        __syncthreads();
        if (wid == 0 && lane < 8) {
            int x = wsum[lane];
#pragma unroll
            for (int o = 1; o < 8; o <<= 1) {
                int u = __shfl_up_sync(0xffu, x, o);
                if (lane >= o) x += u;
            }
            wsum[lane] = x;
        }
        __syncthreads();
        int wbase = (wid > 0) ? wsum[wid - 1] : 0;
        int excl = wbase + v - s;
#pragma unroll
        for (int i = 0; i < 40; i++) {
            int idx = base + i;
            if (idx < N_ATOMS) {
                int o = excl + loc[i];
                g_offsets[idx] = o;
                g_cursor[idx]  = o;
                g_counts[idx]  = 0;   // restore invariant for next replay
            }
        }
        if (tid == 255) {
            g_offsets[N_ATOMS] = wbase + v;
            g_ticket = 0;             // restore invariant for next replay
        }
    }
}

// ---------------- K_prep: scatter + geometry + rbf + f1/f2/f3 GEMM ----------
#define PREP_SMEM (16384 + 8192 + 32768)
__global__ void __launch_bounds__(256) k_prep(
    const int* __restrict__ src, const int* __restrict__ pdst,
    const int* __restrict__ anum,
    const float* __restrict__ dij, const float* __restrict__ rij,
    const float* __restrict__ dp1w, const float* __restrict__ dp2w,
    const float* __restrict__ dp3w,
    const float* __restrict__ dp1b, const float* __restrict__ dp2b,
    const float* __restrict__ dp3b) {
    extern __shared__ char smraw[];
    ulonglong2* sh_dp12 = reinterpret_cast<ulonglong2*>(smraw);          // [r*32+lane]
    ull*        sh_dp3  = reinterpret_cast<ull*>(smraw + 16384);
    float*      s_rbf   = reinterpret_cast<float*>(smraw + 24576);      // [w][p][r]

    int tid = threadIdx.x;
    for (int e = tid; e < R * 32; e += 256) {
        int r = e >> 5, l = e & 31;
        int h0 = 2 * l, h1 = h0 + 1;
        sh_dp12[e] = make_ulonglong2(pk2(dp1w[h0 * R + r], dp1w[h1 * R + r]),
                                     pk2(dp2w[h0 * R + r], dp2w[h1 * R + r]));
        sh_dp3[e]  = pk2(dp3w[h0 * R + r], dp3w[h1 * R + r]);
    }
    __syncthreads();

    int w = tid >> 5, lane = tid & 31;
    int i = blockIdx.x * 256 + tid;
    if ((i & ~31) >= N_PAIRS) return;     // whole warps only (N_PAIRS % 32 == 0)

    // stage 1: geometry + scatter
    float d = dij[i];
    float rc = (d < 0.5f) ? 0.5f * (__cosf(6.2831853071795865f * d) + 1.0f) : 0.0f;
    int za = anum[src[i]];
    int zd = anum[pdst[i]];
    float rx = rij[3 * i], ry = rij[3 * i + 1], rz = rij[3 * i + 2];
    float inv = 1.0f / d;
    float ux = rx * inv, uy = ry * inv, uz = rz * inv;
    float tr3 = (ux * ux + uy * uy + uz * uz) * (1.0f / 3.0f);
    float ee = __expf(-RBF_ALPHA * d);
    int pos = atomicAdd(&g_cursor[src[i]], 1);
    g_geoA[pos] = make_float4(ux, uy, uz, rc);
    g_geoB[pos] = make_float4(ux * ux - tr3, uy * uy - tr3, uz * uz - tr3, 0.0f);
    g_geoC[pos] = make_float4(ux * uy, ux * uz, uy * uz, 0.0f);

    // stage 2: warp-cooperative rbf -> smem [p][r]
    const float rbf_step = (1.0f - RBF_START) * (1.0f / 31.0f);
    float tb = (1.0f - RBF_START) * (2.0f / 32.0f);
    const float beta = 1.0f / (tb * tb);
    const float mlane = RBF_START + rbf_step * (float)lane;
    float* myrbf = s_rbf + w * 1024;
#pragma unroll 4
    for (int j = 0; j < 32; j++) {
        float ee_b = __shfl_sync(0xffffffffu, ee, j);
        float rc_b = __shfl_sync(0xffffffffu, rc, j);
        float dfm = ee_b - mlane;
        myrbf[j * 32 + lane] = __expf(-beta * dfm * dfm) * rc_b;
    }
    __syncwarp();

    float2 b1v = reinterpret_cast<const float2*>(dp1b)[lane];
    float2 b2v = reinterpret_cast<const float2*>(dp2b)[lane];
    float2 b3v = reinterpret_cast<const float2*>(dp3b)[lane];
    ull b1p = pk2(b1v.x, b1v.y);
    ull b2p = pk2(b2v.x, b2v.y);
    ull b3p = pk2(b3v.x, b3v.y);
    const ull tenp = dup2(10.0f);
    const ull hunp = dup2(100.0f);
    const float2* U2 = reinterpret_cast<const float2*>(g_U);
    const float2* V2 = reinterpret_cast<const float2*>(g_V);

    // stage 3: rbf @ W, fold C, write f1/f2/f3
#pragma unroll 1
    for (int grp = 0; grp < 4; grp++) {
        ull g1[8] = {0,0,0,0,0,0,0,0};
        ull g2[8] = {0,0,0,0,0,0,0,0};
        ull g3[8] = {0,0,0,0,0,0,0,0};
        const float* rb = myrbf + grp * 8 * 32;
#pragma unroll
        for (int r = 0; r < R; r++) {
            ulonglong2 w12 = sh_dp12[r * 32 + lane];
            ull w3 = sh_dp3[r * 32 + lane];
#pragma unroll
            for (int pi = 0; pi < 8; pi++) {
                ull rv = dup2(rb[pi * 32 + r]);
                g1[pi] = fma2_(rv, w12.x, g1[pi]);
                g2[pi] = fma2_(rv, w12.y, g2[pi]);
                g3[pi] = fma2_(rv, w3,    g3[pi]);
            }
        }
#pragma unroll
        for (int pi = 0; pi < 8; pi++) {
            int p = grp * 8 + pi;
            int   pos_b = __shfl_sync(0xffffffffu, pos, p);
            int   za_b  = __shfl_sync(0xffffffffu, za,  p);
            int   zd_b  = __shfl_sync(0xffffffffu, zd,  p);
            float rc_b  = __shfl_sync(0xffffffffu, rc,  p);
            float2 ubv = U2[za_b * 32 + lane];
            float2 vbv = V2[zd_b * 32 + lane];
            ull Cp = pk2(rc_b * (ubv.x + vbv.x), rc_b * (ubv.y + vbv.y));
            g_f1[pos_b * 32 + lane] = mul2_(add2_(g1[pi], b1p), Cp);
            g_f2[pos_b * 32 + lane] = mul2_(mul2_(add2_(g2[pi], b2p), Cp), tenp);
            g_f3[pos_b * 32 + lane] = mul2_(mul2_(add2_(g3[pi], b3p), Cp), hunp);
        }
    }
}

// ---------------- K_pairs: pure streaming accumulate + layernorm ----------------
__global__ void __launch_bounds__(256) k_pairs(
    const float* __restrict__ lng, const float* __restrict__ lnb) {
    int w    = threadIdx.x >> 5;
    int lane = threadIdx.x & 31;
    int a    = blockIdx.x * 8 + w;

    int start = g_offsets[a];
    int end   = g_offsets[a + 1];

    ull cI = 0, wx = 0, wy = 0, wz = 0;
    ull sxx = 0, syy = 0, szz = 0, sxy = 0, sxz = 0, syz = 0;

#pragma unroll 2
    for (int idx = start; idx < end; idx++) {
        ull f1 = g_f1[idx * 32 + lane];
        ull f2 = g_f2[idx * 32 + lane];
        ull f3 = g_f3[idx * 32 + lane];
        float4 gA = g_geoA[idx];
        float4 gB = g_geoB[idx];
        float4 gC = g_geoC[idx];
        cI  = add2_(cI, f1);
        wx  = fma2_(f2, dup2(gA.x), wx);
        wy  = fma2_(f2, dup2(gA.y), wy);
        wz  = fma2_(f2, dup2(gA.z), wz);
        sxx = fma2_(f3, dup2(gB.x), sxx);
        syy = fma2_(f3, dup2(gB.y), syy);
        szz = fma2_(f3, dup2(gB.z), szz);
        sxy = fma2_(f3, dup2(gC.x), sxy);
        sxz = fma2_(f3, dup2(gC.y), sxz);
        syz = fma2_(f3, dup2(gC.z), syz);
    }

    float2 cIf = up2(cI),  wxf = up2(wx),  wyf = up2(wy),  wzf = up2(wz);
    float2 sxxf = up2(sxx), syyf = up2(syy), szzf = up2(szz);
    float2 sxyf = up2(sxy), sxzf = up2(sxz), syzf = up2(syz);

    float tA0 = cIf.x + sxxf.x, tB0 = cIf.x + syyf.x, tC0 = cIf.x + szzf.x;
    float tn0 = tA0*tA0 + tB0*tB0 + tC0*tC0
              + 2.0f * (sxyf.x*sxyf.x + wzf.x*wzf.x + sxzf.x*sxzf.x
                      + wyf.x*wyf.x + syzf.x*syzf.x + wxf.x*wxf.x);
    float tA1 = cIf.y + sxxf.y, tB1 = cIf.y + syyf.y, tC1 = cIf.y + szzf.y;
    float tn1 = tA1*tA1 + tB1*tB1 + tC1*tC1
              + 2.0f * (sxyf.y*sxyf.y + wzf.y*wzf.y + sxzf.y*sxzf.y
                      + wyf.y*wyf.y + syzf.y*syzf.y + wxf.y*wxf.y);

    float ssum = tn0 + tn1;
#pragma unroll
    for (int o = 16; o; o >>= 1) ssum += __shfl_xor_sync(0xffffffffu, ssum, o);
    float mu = ssum * (1.0f / 64.0f);
    float e0 = tn0 - mu, e1 = tn1 - mu;
    float vsum = e0 * e0 + e1 * e1;
#pragma unroll
    for (int o = 16; o; o >>= 1) vsum += __shfl_xor_sync(0xffffffffu, vsum, o);
    float rstd = rsqrtf(vsum * (1.0f / 64.0f) + 1e-5f);

    float2 lg = reinterpret_cast<const float2*>(lng)[lane];
    float2 lb = reinterpret_cast<const float2*>(lnb)[lane];
    float2 nrm;
    nrm.x = e0 * rstd * lg.x + lb.x;
    nrm.y = e1 * rstd * lg.y + lb.y;
    reinterpret_cast<float2*>(g_tnorm)[a * 32 + lane] = nrm;

    int oidx = a * 32 + lane;
    reinterpret_cast<float2*>(g_comp[0])[oidx] = cIf;
    reinterpret_cast<float2*>(g_comp[1])[oidx] = wxf;
    reinterpret_cast<float2*>(g_comp[2])[oidx] = wyf;
    reinterpret_cast<float2*>(g_comp[3])[oidx] = wzf;
    reinterpret_cast<float2*>(g_comp[4])[oidx] = sxxf;
    reinterpret_cast<float2*>(g_comp[5])[oidx] = syyf;
    reinterpret_cast<float2*>(g_comp[6])[oidx] = szzf;
    reinterpret_cast<float2*>(g_comp[7])[oidx] = sxyf;
    reinterpret_cast<float2*>(g_comp[8])[oidx] = sxzf;
    reinterpret_cast<float2*>(g_comp[9])[oidx] = syzf;
}

// ---------------- K_mlpfinal: 8 atoms/block, 320 threads, 4 blocks/SM --------
// smem (ull): region[3200] (csh [c][h][q4]=c*256+h*4 (2560) then res [c][g][q5]=c*320+g*5 (3200))
//             nshT[256] ([k][q4]=k*4), h1T[512] ([hq][j][i]=hq*256+j*2+i),
//             nm float[1536] = 768 ull ([atom][j2])
#define MLPF_ULL (3200 + 256 + 512 + 768)
#define MLPF_SMEM (MLPF_ULL * 8)
__global__ void __launch_bounds__(320, 4) k_mlpfinal(
    const float* __restrict__ ls1b, const float* __restrict__ ls2b,
    float* __restrict__ out) {
    extern __shared__ __align__(16) ull smu[];
    ull*   region = smu;
    ull*   nshT   = smu + 3200;
    ull*   h1T    = smu + 3456;
    float* nm     = reinterpret_cast<float*>(smu + 3968);   // 1536 floats
    float* resf   = reinterpret_cast<float*>(region);

    int tid = threadIdx.x;
    int ab  = blockIdx.x * 8;

    // ---- stage csh [c][h][q4 in {0,1}] -> 2 ull (4 atoms) per unit
#pragma unroll
    for (int it = 0; it < 4; it++) {
        int u = it * 320 + tid;          // < 1280
        int q4 = u & 1;
        int h  = (u >> 1) & 63;
        int c  = u >> 7;                 // 0..9
        const float* cp = g_comp[c] + (ab + 4 * q4) * 64 + h;
        float v0 = cp[0], v1 = cp[64], v2 = cp[128], v3 = cp[192];
        *reinterpret_cast<ulonglong2*>(region + c * 256 + h * 4 + 2 * q4) =
            make_ulonglong2(pk2(v0, v1), pk2(v2, v3));
    }
    // ---- stage nshT [k][q4]
    if (tid < 128) {
        int q4 = tid & 1;
        int k  = tid >> 1;
        const float* tp = g_tnorm + (ab + 4 * q4) * 64 + k;
        float v0 = tp[0], v1 = tp[64], v2 = tp[128], v3 = tp[192];
        *reinterpret_cast<ulonglong2*>(nshT + k * 4 + 2 * q4) =
            make_ulonglong2(pk2(v0, v1), pk2(v2, v3));
    }
    __syncthreads();

    // ---- channel-mix GEMM: thread = (c, gl); handles g=gl and g=gl+32, 8 atoms
    ull accA[4], accB[4];
    int c = tid >> 5, gl = tid & 31;
    {
        int m = (c == 0) ? 0 : (c < 4) ? 1 : 2;
        const float4* wq = reinterpret_cast<const float4*>(g_ltT4 + m * 4096);
        const ull* csrc = region + c * 256;
#pragma unroll
        for (int i = 0; i < 4; i++) { accA[i] = 0ull; accB[i] = 0ull; }
#pragma unroll 4
        for (int t = 0; t < 16; t++) {
            float4 wvA = wq[t * 64 + gl];
            float4 wvB = wq[t * 64 + gl + 32];
#pragma unroll
            for (int kk = 0; kk < 4; kk++) {
                float wsA = (kk == 0) ? wvA.x : (kk == 1) ? wvA.y : (kk == 2) ? wvA.z : wvA.w;
                float wsB = (kk == 0) ? wvB.x : (kk == 1) ? wvB.y : (kk == 2) ? wvB.z : wvB.w;
                ull wdA = dup2(wsA), wdB = dup2(wsB);
                const ulonglong2* q =
                    reinterpret_cast<const ulonglong2*>(csrc + (4 * t + kk) * 4);
                ulonglong2 q0 = q[0], q1 = q[1];      // broadcast: 4 ull = 8 atoms
                accA[0] = fma2_(wdA, q0.x, accA[0]);
                accA[1] = fma2_(wdA, q0.y, accA[1]);
                accA[2] = fma2_(wdA, q1.x, accA[2]);
                accA[3] = fma2_(wdA, q1.y, accA[3]);
                accB[0] = fma2_(wdB, q0.x, accB[0]);
                accB[1] = fma2_(wdB, q0.y, accB[1]);
                accB[2] = fma2_(wdB, q1.x, accB[2]);
                accB[3] = fma2_(wdB, q1.y, accB[3]);
            }
        }
    }
    __syncthreads();   // all csh reads done; region reusable as res

    // ---- write res [c][g][q-pad5] + MLP layer 1
    {
        ull* rpA = region + c * 320 + gl * 5;
        ull* rpB = region + c * 320 + (gl + 32) * 5;
#pragma unroll
        for (int i = 0; i < 4; i++) { rpA[i] = accA[i]; rpB[i] = accB[i]; }
    }
    if (tid < 256) {
        int j = tid & 127, hq = tid >> 7;       // hq 0..1 -> atoms 4hq..4hq+3
        ull bp = dup2(ls1b[j]);
        ull a0 = bp, a1 = bp;
        const ull* wcol = g_ls1D + j;
#pragma unroll 8
        for (int k = 0; k < 64; k++) {
            ull wd = wcol[k * 128];
            ulonglong2 hv = *reinterpret_cast<const ulonglong2*>(nshT + k * 4 + 2 * hq);
            a0 = fma2_(wd, hv.x, a0);
            a1 = fma2_(wd, hv.y, a1);
        }
        float2 f0 = up2(a0), f1v = up2(a1);
        float r0 = f0.x  / (1.0f + __expf(-f0.x));
        float r1 = f0.y  / (1.0f + __expf(-f0.y));
        float r2 = f1v.x / (1.0f + __expf(-f1v.x));
        float r3 = f1v.y / (1.0f + __expf(-f1v.y));
        *reinterpret_cast<ulonglong2*>(h1T + hq * 256 + j * 2) =
            make_ulonglong2(pk2(r0, r1), pk2(r2, r3));
    }
    __syncthreads();

    // ---- MLP layer 2: 192 threads = (jp 0..95, atom-quad aq 0..1); 4 accs each
    if (tid < 192) {
        int jp = tid % 96, aq = tid / 96;
        int j2a = 2 * jp, j2b = j2a + 1;
        ull acc2[4];
        {
            ull bpa = dup2(ls2b[j2a]);
            ull bpb = dup2(ls2b[j2b]);
            acc2[0] = bpa; acc2[1] = bpa;
            acc2[2] = bpb; acc2[3] = bpb;
        }
        const ull* hq = h1T + aq * 256;   // atoms 4aq..4aq+3
#pragma unroll 4
        for (int k = 0; k < 128; k++) {
            float2 wp = reinterpret_cast<const float2*>(g_ls2T + k * 192)[jp];
            ull wda = dup2(wp.x), wdb = dup2(wp.y);
            ulonglong2 hv = *reinterpret_cast<const ulonglong2*>(hq + k * 2);
            acc2[0] = fma2_(wda, hv.x, acc2[0]);
            acc2[1] = fma2_(wda, hv.y, acc2[1]);
            acc2[2] = fma2_(wdb, hv.x, acc2[2]);
            acc2[3] = fma2_(wdb, hv.y, acc2[3]);
        }
#pragma unroll
        for (int i = 0; i < 2; i++) {
            int a0i = 4 * aq + 2 * i;
            float2 fa = up2(acc2[i]);
            nm[a0i * 192 + j2a]       = fa.x / (1.0f + __expf(-fa.x));
            nm[(a0i + 1) * 192 + j2a] = fa.y / (1.0f + __expf(-fa.y));
            float2 fb = up2(acc2[2 + i]);
            nm[a0i * 192 + j2b]       = fb.x / (1.0f + __expf(-fb.x));
            nm[(a0i + 1) * 192 + j2b] = fb.y / (1.0f + __expf(-fb.y));
        }
    }
    __syncthreads();

    // ---- assemble 3x3 outputs: thread = (aa = tid/40, w0 = tid%40), stride 40
    {
        int aa = tid / 40;            // 0..7 (320 = 8*40)
        int w0 = tid - aa * 40;       // 0..39
        int g2 = w0 / 9;
        int ij = w0 - g2 * 9;
        float* ob = out + (ab + aa) * 576;
        const float* nmb = nm + aa * 192;
        const float* rb = resf + aa;       // res float view: c*640 + g*10 + atom
        for (int idx = w0; idx < 576; idx += 40) {
            int i3 = (ij * 11) >> 5;
            int jc = ij - i3 * 3;
            bool dg = (i3 == jc);
            int sidx = dg ? (4 + i3) : (6 + i3 + jc);
            int aidx = dg ? 1 : (4 - (i3 + jc));
            float sgn = dg ? 0.0f : ((((i3 - jc) + 3) % 3 == 1) ? 1.0f : -1.0f);
            float n0 = nmb[g2 * 3 + 0];
            float n1 = nmb[g2 * 3 + 1];
            float n2 = nmb[g2 * 3 + 2];
            float cIv = rb[g2 * 10];
            float av  = rb[aidx * 640 + g2 * 10];
            float sv  = rb[sidx * 640 + g2 * 10];
            float iv = dg ? cIv : 0.0f;
            ob[idx] = iv * n0 + sgn * av * n1 + sv * n2;
            ij += 4; g2 += 4;
            if (ij >= 9) { ij -= 9; g2 += 1; }
        }
    }
}

// ---------------- launch ----------------
extern "C" void kernel_launch(void* const* d_in, const int* in_sizes, int n_in,
                              void* d_out, int out_size) {
    const int*   anum  = (const int*)d_in[0];
    const int*   psrc  = (const int*)d_in[1];
    const int*   pdst  = psrc + N_PAIRS;
    const float* dij   = (const float*)d_in[2];
    const float* rij   = (const float*)d_in[3];
    const float* emb   = (const float*)d_in[4];
    const float* e2w   = (const float*)d_in[5];
    const float* e2b   = (const float*)d_in[6];
    const float* dp1w  = (const float*)d_in[7];
    const float* dp1b  = (const float*)d_in[8];
    const float* dp2w  = (const float*)d_in[9];
    const float* dp2b  = (const float*)d_in[10];
    const float* dp3w  = (const float*)d_in[11];
    const float* dp3b  = (const float*)d_in[12];
    const float* lt0   = (const float*)d_in[13];
    const float* lt1   = (const float*)d_in[14];
    const float* lt2   = (const float*)d_in[15];
    const float* ls1w  = (const float*)d_in[16];
    const float* ls1b  = (const float*)d_in[17];
    const float* ls2w  = (const float*)d_in[18];
    const float* ls2b  = (const float*)d_in[19];
    const float* lng   = (const float*)d_in[20];
    const float* lnb   = (const float*)d_in[21];
    float* out = (float*)d_out;

    cudaFuncSetAttribute(k_prep, cudaFuncAttributeMaxDynamicSharedMemorySize, PREP_SMEM);
    cudaFuncSetAttribute(k_mlpfinal, cudaFuncAttributeMaxDynamicSharedMemorySize, MLPF_SMEM);

    k_pre<<<PRE_BLOCKS, 256>>>(psrc, emb, e2w, e2b, lt0, lt1, lt2, ls1w, ls2w);
    k_prep<<<(N_PAIRS + 255) / 256, 256, PREP_SMEM>>>(psrc, pdst, anum, dij, rij,
                                                      dp1w, dp2w, dp3w,
                                                      dp1b, dp2b, dp3b);
    k_pairs<<<N_ATOMS / 8, 256>>>(lng, lnb);
    k_mlpfinal<<<N_ATOMS / 8, 320, MLPF_SMEM>>>(ls1b, ls2b, out);
}